// round 3
// baseline (speedup 1.0000x reference)
#include <cuda_runtime.h>
#include <cstdint>

// Problem constants
#define BB      1024
#define CC      64
#define WW      40
#define NPROT   40
#define NCLS    512
#define PP      (NPROT * NCLS)   // 20480

// ---------------------------------------------------------------------------
// Scratch (device globals, allowed; no dynamic allocation)
// ---------------------------------------------------------------------------
__device__ __align__(16) float g_xn [NPROT * BB * CC];     // [i][b][c]   10.5 MB
__device__ __align__(16) float g_pn [NPROT * NCLS * CC];   // [i][a][c]    5.25 MB
__device__ __align__(16) float g_sim[(size_t)BB * NPROT * NCLS]; // [b][i][a] 84 MB
__device__ __align__(16) float g_acc[BB * NCLS];           // S_n(b)       2 MB

// ---------------------------------------------------------------------------
// f32x2 packed helpers (Blackwell sm_103a)
// ---------------------------------------------------------------------------
__device__ __forceinline__ unsigned long long pk2(float lo, float hi) {
    unsigned long long r;
    asm("mov.b64 %0, {%1, %2};" : "=l"(r) : "f"(lo), "f"(hi));
    return r;
}
__device__ __forceinline__ void fma2(unsigned long long& d,
                                     unsigned long long a,
                                     unsigned long long b) {
    asm("fma.rn.f32x2 %0, %1, %2, %0;" : "+l"(d) : "l"(a), "l"(b));
}
__device__ __forceinline__ float2 upk2(unsigned long long v) {
    float2 r;
    asm("mov.b64 {%0, %1}, %2;" : "=f"(r.x), "=f"(r.y) : "l"(v));
    return r;
}

// ---------------------------------------------------------------------------
// K1: normalize prototypes over C and reorder to g_pn[i][a][c]
//     i = p % 40, a = p / 40.  One warp per prototype, 8 protos / block.
// ---------------------------------------------------------------------------
__global__ void k1_norm_proto(const float* __restrict__ proto) {
    int p    = blockIdx.x * 8 + (threadIdx.x >> 5);
    int lane = threadIdx.x & 31;
    if (p >= PP) return;
    float v0 = proto[p * CC + lane];
    float v1 = proto[p * CC + lane + 32];
    float ss = v0 * v0 + v1 * v1;
    #pragma unroll
    for (int o = 16; o; o >>= 1) ss += __shfl_xor_sync(0xffffffffu, ss, o);
    float sc = 1.0f / fmaxf(sqrtf(ss), 1e-12f);
    int i = p % NPROT, a = p / NPROT;
    float* dst = &g_pn[(i * NCLS + a) * CC];
    dst[lane]      = v0 * sc;
    dst[lane + 32] = v1 * sc;
}

// ---------------------------------------------------------------------------
// K2: normalize conv_features over C (per b,w), reorder to g_xn[i][b][c].
//     One block per b; coalesced load of the (64 x 40) slab, smem transpose.
// ---------------------------------------------------------------------------
__global__ void k2_norm_x(const float* __restrict__ conv) {
    __shared__ float s[CC * 41];     // [c][w], pad 41 -> conflict-free columns
    __shared__ float rn[WW];
    int b = blockIdx.x;
    int t = threadIdx.x;             // 256 threads
    const float* src = conv + (size_t)b * (CC * WW);
    for (int e = t; e < CC * WW; e += 256) {
        int c = e / WW, w = e % WW;
        s[c * 41 + w] = src[e];
    }
    __syncthreads();
    if (t < WW) {
        float ss = 0.0f;
        #pragma unroll
        for (int c = 0; c < CC; ++c) { float v = s[c * 41 + t]; ss += v * v; }
        rn[t] = 1.0f / fmaxf(sqrtf(ss), 1e-12f);
    }
    __syncthreads();
    for (int e = t; e < WW * CC; e += 256) {
        int i = e / CC, c = e % CC;
        g_xn[((size_t)i * BB + b) * CC + c] = s[c * 41 + i] * rn[i];
    }
}

// ---------------------------------------------------------------------------
// K3: 40 GEMMs (z = i): sim[b, i, a] = dot_c( xn[i][b][:], pn[i][a][:] )
//     Tile 128x128, K=64 in two 32-wide phases, 8x8 per thread, f32x2 FMA.
// ---------------------------------------------------------------------------
#define PAD 132   // multiple of 4 for 16B-aligned smem float4 reads

__global__ __launch_bounds__(256, 2) void k3_gemm() {
    __shared__ float As[32 * PAD];   // [k][m]
    __shared__ float Bs[32 * PAD];   // [k][n]
    const int i  = blockIdx.z;
    const int b0 = blockIdx.y * 128;
    const int a0 = blockIdx.x * 128;
    const int t  = threadIdx.x;
    const float* Ag = g_xn + ((size_t)i * BB + b0) * CC;
    const float* Bg = g_pn + ((size_t)i * NCLS + a0) * CC;
    const int m0 = (t & 15) * 8;
    const int n0 = (t >> 4) * 8;

    unsigned long long acc[8][4];
    #pragma unroll
    for (int m = 0; m < 8; ++m)
        #pragma unroll
        for (int j = 0; j < 4; ++j) acc[m][j] = 0ull;

    for (int kk = 0; kk < CC; kk += 32) {
        __syncthreads();
        // Load 128 rows x 32 cols of each operand into [k][row] layout.
        #pragma unroll
        for (int j = 0; j < 4; ++j) {
            int idx = t + j * 256;          // float4 index, 0..1023
            int row = idx >> 3;             // 0..127
            int c4  = idx & 7;              // 0..7
            float4 va = *(const float4*)(Ag + row * CC + kk + c4 * 4);
            As[(c4 * 4 + 0) * PAD + row] = va.x;
            As[(c4 * 4 + 1) * PAD + row] = va.y;
            As[(c4 * 4 + 2) * PAD + row] = va.z;
            As[(c4 * 4 + 3) * PAD + row] = va.w;
            float4 vb = *(const float4*)(Bg + row * CC + kk + c4 * 4);
            Bs[(c4 * 4 + 0) * PAD + row] = vb.x;
            Bs[(c4 * 4 + 1) * PAD + row] = vb.y;
            Bs[(c4 * 4 + 2) * PAD + row] = vb.z;
            Bs[(c4 * 4 + 3) * PAD + row] = vb.w;
        }
        __syncthreads();
        #pragma unroll 8
        for (int k = 0; k < 32; ++k) {
            const float4 alo = *(const float4*)(As + k * PAD + m0);
            const float4 ahi = *(const float4*)(As + k * PAD + m0 + 4);
            const float4 blo = *(const float4*)(Bs + k * PAD + n0);
            const float4 bhi = *(const float4*)(Bs + k * PAD + n0 + 4);
            unsigned long long bp0 = pk2(blo.x, blo.y);
            unsigned long long bp1 = pk2(blo.z, blo.w);
            unsigned long long bp2 = pk2(bhi.x, bhi.y);
            unsigned long long bp3 = pk2(bhi.z, bhi.w);
            float am[8] = {alo.x, alo.y, alo.z, alo.w, ahi.x, ahi.y, ahi.z, ahi.w};
            #pragma unroll
            for (int m = 0; m < 8; ++m) {
                unsigned long long ap = pk2(am[m], am[m]);
                fma2(acc[m][0], ap, bp0);
                fma2(acc[m][1], ap, bp1);
                fma2(acc[m][2], ap, bp2);
                fma2(acc[m][3], ap, bp3);
            }
        }
    }

    // Epilogue: sim scratch [b][i][a], coalesced float4 stores.
    #pragma unroll
    for (int m = 0; m < 8; ++m) {
        float2 p0 = upk2(acc[m][0]);
        float2 p1 = upk2(acc[m][1]);
        float2 p2 = upk2(acc[m][2]);
        float2 p3 = upk2(acc[m][3]);
        float4 lo = make_float4(p0.x, p0.y, p1.x, p1.y);
        float4 hi = make_float4(p2.x, p2.y, p3.x, p3.y);
        float* row = g_sim + (size_t)(b0 + m0 + m) * (NPROT * NCLS)
                           + (size_t)i * NCLS + a0 + n0;
        *(float4*)(row)     = lo;
        *(float4*)(row + 4) = hi;
    }
}

// ---------------------------------------------------------------------------
// K4: per (b, 64-wide a-chunk): transpose [i][a] -> [a][i] (p = 40a + i),
//     write min_distances = -sim coalesced; also S_n(b) partial column sums.
// ---------------------------------------------------------------------------
__global__ void k4_transpose(float* __restrict__ out_md) {
    __shared__ float s[WW * 65];     // [i][a], pad 65
    int b  = blockIdx.y;
    int a0 = blockIdx.x * 64;
    int t  = threadIdx.x;            // 256 threads
    const float* src = g_sim + (size_t)b * (NPROT * NCLS);
    for (int e = t; e < WW * 64; e += 256) {
        int i = e / 64, a = e % 64;
        s[i * 65 + a] = src[(size_t)i * NCLS + a0 + a];
    }
    __syncthreads();
    if (t < 64) {
        float sum = 0.0f;
        #pragma unroll
        for (int i = 0; i < WW; ++i) sum += s[i * 65 + t];
        g_acc[b * NCLS + a0 + t] = sum;
    }
    float* dst = out_md + (size_t)b * PP + (size_t)a0 * NPROT;
    for (int e = t; e < 64 * WW; e += 256) {
        int a = e / WW, i = e % WW;
        dst[e] = -s[i * 65 + a];
    }
}

// ---------------------------------------------------------------------------
// K5: logits[b][n] = 1.5 * S_n(b) - 0.5 * sum_n S_n(b)
// ---------------------------------------------------------------------------
__global__ void k5_logits(float* __restrict__ out_logits) {
    __shared__ float warpsum[16];
    __shared__ float stot;
    int b = blockIdx.x;
    int t = threadIdx.x;             // 512 threads
    float v = g_acc[b * NCLS + t];
    float s = v;
    #pragma unroll
    for (int o = 16; o; o >>= 1) s += __shfl_xor_sync(0xffffffffu, s, o);
    if ((t & 31) == 0) warpsum[t >> 5] = s;
    __syncthreads();
    if (t == 0) {
        float x = 0.0f;
        #pragma unroll
        for (int w = 0; w < 16; ++w) x += warpsum[w];
        stot = x;
    }
    __syncthreads();
    out_logits[b * NCLS + t] = 1.5f * v - 0.5f * stot;
}

// ---------------------------------------------------------------------------
// Launch: inputs = conv_features, prototype, last_layer_weight (unused),
//         offset_tensor (unused).  Output = [logits (B*512) | min_dist (B*20480)]
// ---------------------------------------------------------------------------
extern "C" void kernel_launch(void* const* d_in, const int* in_sizes, int n_in,
                              void* d_out, int out_size) {
    (void)in_sizes; (void)n_in; (void)out_size;
    const float* conv  = (const float*)d_in[0];
    const float* proto = (const float*)d_in[1];
    float* out        = (float*)d_out;
    float* out_logits = out;
    float* out_md     = out + (size_t)BB * NCLS;

    k1_norm_proto<<<PP / 8, 256>>>(proto);
    k2_norm_x<<<BB, 256>>>(conv);
    dim3 g3(NCLS / 128, BB / 128, NPROT);
    k3_gemm<<<g3, 256>>>();
    dim3 g4(NCLS / 64, BB);
    k4_transpose<<<g4, 256>>>(out_md);
    k5_logits<<<BB, 512>>>(out_logits);
}

// round 4
// speedup vs baseline: 1.2315x; 1.2315x over previous
#include <cuda_runtime.h>
#include <cstdint>

// Problem constants
#define BB      1024
#define CC      64
#define WW      40
#define NPROT   40
#define NCLS    512
#define PP      (NPROT * NCLS)   // 20480

// ---------------------------------------------------------------------------
// Scratch (device globals; no dynamic allocation)
// ---------------------------------------------------------------------------
__device__ __align__(16) float g_xn [NPROT * BB * CC];     // [i][b][c]
__device__ __align__(16) float g_pn [NPROT * NCLS * CC];   // [i][a][c]
__device__ __align__(16) float g_sim[(size_t)BB * NPROT * NCLS]; // [b][i][a]
__device__ __align__(16) float g_acc[BB * NCLS];           // S_n(b)

// ---------------------------------------------------------------------------
// f32x2 packed helpers (sm_103a)
// ---------------------------------------------------------------------------
__device__ __forceinline__ unsigned long long pk2(float lo, float hi) {
    unsigned long long r;
    asm("mov.b64 %0, {%1, %2};" : "=l"(r) : "f"(lo), "f"(hi));
    return r;
}
__device__ __forceinline__ void fma2(unsigned long long& d,
                                     unsigned long long a,
                                     unsigned long long b) {
    asm("fma.rn.f32x2 %0, %1, %2, %0;" : "+l"(d) : "l"(a), "l"(b));
}
__device__ __forceinline__ float2 upk2(unsigned long long v) {
    float2 r;
    asm("mov.b64 {%0, %1}, %2;" : "=f"(r.x), "=f"(r.y) : "l"(v));
    return r;
}

// ---------------------------------------------------------------------------
// K1: normalize prototypes over C, reorder to g_pn[i][a][c]
// ---------------------------------------------------------------------------
__global__ void k1_norm_proto(const float* __restrict__ proto) {
    int p    = blockIdx.x * 8 + (threadIdx.x >> 5);
    int lane = threadIdx.x & 31;
    if (p >= PP) return;
    float v0 = proto[p * CC + lane];
    float v1 = proto[p * CC + lane + 32];
    float ss = v0 * v0 + v1 * v1;
    #pragma unroll
    for (int o = 16; o; o >>= 1) ss += __shfl_xor_sync(0xffffffffu, ss, o);
    float sc = 1.0f / fmaxf(sqrtf(ss), 1e-12f);
    int i = p % NPROT, a = p / NPROT;
    float* dst = &g_pn[(i * NCLS + a) * CC];
    dst[lane]      = v0 * sc;
    dst[lane + 32] = v1 * sc;
}

// ---------------------------------------------------------------------------
// K2: normalize conv_features over C (per b,w), reorder to g_xn[i][b][c]
// ---------------------------------------------------------------------------
__global__ void k2_norm_x(const float* __restrict__ conv) {
    __shared__ float s[CC * 41];
    __shared__ float rn[WW];
    int b = blockIdx.x;
    int t = threadIdx.x;             // 256
    const float* src = conv + (size_t)b * (CC * WW);
    for (int e = t; e < CC * WW; e += 256) {
        int c = e / WW, w = e % WW;
        s[c * 41 + w] = src[e];
    }
    __syncthreads();
    if (t < WW) {
        float ss = 0.0f;
        #pragma unroll
        for (int c = 0; c < CC; ++c) { float v = s[c * 41 + t]; ss += v * v; }
        rn[t] = 1.0f / fmaxf(sqrtf(ss), 1e-12f);
    }
    __syncthreads();
    for (int e = t; e < WW * CC; e += 256) {
        int i = e / CC, c = e % CC;
        g_xn[((size_t)i * BB + b) * CC + c] = s[c * 41 + i] * rn[i];
    }
}

// ---------------------------------------------------------------------------
// K3: 40 GEMMs (z = i): sim[b, i, a] = dot_c( xn[i][b][:], pn[i][a][:] )
//     128x128 tile, single K=64 phase, split 8x8 thread tile
//     (m in {m0..m0+3} U {m0+64..m0+67}) -> conflict-free compute LDS.
// ---------------------------------------------------------------------------
#define PAD 132   // multiple of 4; chunk pitch 33 (odd) rotates banks per k

extern __shared__ float sm3[];

__global__ __launch_bounds__(256, 2) void k3_gemm() {
    float* As = sm3;                 // [k=64][m=128] pitch PAD
    float* Bs = sm3 + 64 * PAD;      // [k=64][n=128] pitch PAD
    const int i  = blockIdx.z;
    const int b0 = blockIdx.y * 128;
    const int a0 = blockIdx.x * 128;
    const int t  = threadIdx.x;
    const float4* Ag = (const float4*)(g_xn + ((size_t)i * BB + b0) * CC);
    const float4* Bg = (const float4*)(g_pn + ((size_t)i * NCLS + a0) * CC);
    const int m0 = (t & 15) * 4;
    const int n0 = (t >> 4) * 4;

    // Fill: 128 rows x 16 float4 per operand; transpose to [k][row].
    #pragma unroll
    for (int j = 0; j < 8; ++j) {
        int idx = t + j * 256;           // 0..2047
        int row = idx >> 4;              // 0..127
        int c4  = idx & 15;              // 0..15
        float4 va = Ag[row * 16 + c4];
        As[(c4 * 4 + 0) * PAD + row] = va.x;
        As[(c4 * 4 + 1) * PAD + row] = va.y;
        As[(c4 * 4 + 2) * PAD + row] = va.z;
        As[(c4 * 4 + 3) * PAD + row] = va.w;
        float4 vb = Bg[row * 16 + c4];
        Bs[(c4 * 4 + 0) * PAD + row] = vb.x;
        Bs[(c4 * 4 + 1) * PAD + row] = vb.y;
        Bs[(c4 * 4 + 2) * PAD + row] = vb.z;
        Bs[(c4 * 4 + 3) * PAD + row] = vb.w;
    }
    __syncthreads();

    // acc[m 0..7][nj 0..3]; m = mh*4+mm (row b0 + mh*64 + m0 + mm)
    // nj 0,1 -> cols a0+n0+{0,1},{2,3}; nj 2,3 -> cols a0+64+n0+{0..3}
    unsigned long long acc[8][4];
    #pragma unroll
    for (int m = 0; m < 8; ++m)
        #pragma unroll
        for (int j = 0; j < 4; ++j) acc[m][j] = 0ull;

    #pragma unroll 8
    for (int k = 0; k < 64; ++k) {
        const float* ak = As + k * PAD;
        const float* bk = Bs + k * PAD;
        const float4 alo = *(const float4*)(ak + m0);
        const float4 ahi = *(const float4*)(ak + 64 + m0);
        const float4 blo = *(const float4*)(bk + n0);
        const float4 bhi = *(const float4*)(bk + 64 + n0);
        unsigned long long bp0 = pk2(blo.x, blo.y);
        unsigned long long bp1 = pk2(blo.z, blo.w);
        unsigned long long bp2 = pk2(bhi.x, bhi.y);
        unsigned long long bp3 = pk2(bhi.z, bhi.w);
        float am[8] = {alo.x, alo.y, alo.z, alo.w, ahi.x, ahi.y, ahi.z, ahi.w};
        #pragma unroll
        for (int m = 0; m < 8; ++m) {
            unsigned long long ap = pk2(am[m], am[m]);
            fma2(acc[m][0], ap, bp0);
            fma2(acc[m][1], ap, bp1);
            fma2(acc[m][2], ap, bp2);
            fma2(acc[m][3], ap, bp3);
        }
    }

    // Epilogue: g_sim[b][i][a], two float4 per m-row (cols n0 and 64+n0).
    #pragma unroll
    for (int m = 0; m < 8; ++m) {
        int row = b0 + ((m >> 2) << 6) + m0 + (m & 3);
        float2 p0 = upk2(acc[m][0]);
        float2 p1 = upk2(acc[m][1]);
        float2 p2 = upk2(acc[m][2]);
        float2 p3 = upk2(acc[m][3]);
        float* base = g_sim + (size_t)row * (NPROT * NCLS) + (size_t)i * NCLS + a0;
        *(float4*)(base + n0)      = make_float4(p0.x, p0.y, p1.x, p1.y);
        *(float4*)(base + 64 + n0) = make_float4(p2.x, p2.y, p3.x, p3.y);
    }
}

// ---------------------------------------------------------------------------
// K4: per (b, 128-wide a-chunk): vectorized transpose [i][a] -> [a][i],
//     write min_distances = -sim via STG.128; also S_n(b) column sums.
// ---------------------------------------------------------------------------
__global__ __launch_bounds__(256) void k4_transpose(float* __restrict__ out_md) {
    __shared__ float s[128 * 41];    // [a][i], pitch 41
    int b  = blockIdx.y;
    int a0 = blockIdx.x * 128;
    int t  = threadIdx.x;            // 256
    const float4* src4 = (const float4*)(g_sim + (size_t)b * (NPROT * NCLS));
    const int a0_4 = a0 >> 2;

    #pragma unroll
    for (int kk = 0; kk < 5; ++kk) {
        int j  = t + kk * 256;       // 0..1279
        int i  = j >> 5;             // 0..39
        int a4 = j & 31;             // 0..31
        float4 v = src4[i * 128 + a0_4 + a4];
        float* p = s + (a4 * 4) * 41 + i;
        p[0]       = v.x;
        p[41]      = v.y;
        p[82]      = v.z;
        p[123]     = v.w;
    }
    __syncthreads();

    if (t < 128) {
        float sum = 0.0f;
        const float* p = s + t * 41;
        #pragma unroll
        for (int i = 0; i < WW; ++i) sum += p[i];
        g_acc[b * NCLS + a0 + t] = sum;
    }

    float4* dst4 = (float4*)(out_md + (size_t)b * PP + (size_t)a0 * NPROT);
    #pragma unroll
    for (int kk = 0; kk < 5; ++kk) {
        int e4 = t + kk * 256;       // 0..1279
        int a  = e4 / 10;            // const div -> mul.hi
        int i0 = (e4 - a * 10) * 4;
        const float* p = s + a * 41 + i0;
        float4 o;
        o.x = -p[0]; o.y = -p[1]; o.z = -p[2]; o.w = -p[3];
        dst4[e4] = o;
    }
}

// ---------------------------------------------------------------------------
// K5: logits[b][n] = 1.5 * S_n(b) - 0.5 * sum_n S_n(b)
// ---------------------------------------------------------------------------
__global__ void k5_logits(float* __restrict__ out_logits) {
    __shared__ float warpsum[16];
    __shared__ float stot;
    int b = blockIdx.x;
    int t = threadIdx.x;             // 512
    float v = g_acc[b * NCLS + t];
    float sx = v;
    #pragma unroll
    for (int o = 16; o; o >>= 1) sx += __shfl_xor_sync(0xffffffffu, sx, o);
    if ((t & 31) == 0) warpsum[t >> 5] = sx;
    __syncthreads();
    if (t == 0) {
        float x = 0.0f;
        #pragma unroll
        for (int w = 0; w < 16; ++w) x += warpsum[w];
        stot = x;
    }
    __syncthreads();
    out_logits[b * NCLS + t] = 1.5f * v - 0.5f * stot;
}

// ---------------------------------------------------------------------------
// Launch
// ---------------------------------------------------------------------------
extern "C" void kernel_launch(void* const* d_in, const int* in_sizes, int n_in,
                              void* d_out, int out_size) {
    (void)in_sizes; (void)n_in; (void)out_size;
    const float* conv  = (const float*)d_in[0];
    const float* proto = (const float*)d_in[1];
    float* out        = (float*)d_out;
    float* out_logits = out;
    float* out_md     = out + (size_t)BB * NCLS;

    const int k3_smem = 2 * 64 * PAD * (int)sizeof(float);   // 67584 B
    cudaFuncSetAttribute(k3_gemm, cudaFuncAttributeMaxDynamicSharedMemorySize,
                         k3_smem);

    k1_norm_proto<<<PP / 8, 256>>>(proto);
    k2_norm_x<<<BB, 256>>>(conv);
    dim3 g3(NCLS / 128, BB / 128, NPROT);
    k3_gemm<<<g3, 256, k3_smem>>>();
    dim3 g4(NCLS / 128, BB);
    k4_transpose<<<g4, 256>>>(out_md);
    k5_logits<<<BB, 512>>>(out_logits);
}

// round 7
// speedup vs baseline: 1.9359x; 1.5721x over previous
#include <cuda_runtime.h>
#include <cuda_bf16.h>
#include <cstdint>

// Problem constants
#define BB      1024
#define CC      64
#define WW      40
#define NPROT   40
#define NCLS    512
#define PP      (NPROT * NCLS)   // 20480

// ---------------------------------------------------------------------------
// Scratch (device globals; no dynamic allocation)
// ---------------------------------------------------------------------------
__device__ __align__(16) __nv_bfloat16 g_xh[NPROT * BB * CC];    // [i][b][c] hi
__device__ __align__(16) __nv_bfloat16 g_xl[NPROT * BB * CC];    // [i][b][c] lo
__device__ __align__(16) __nv_bfloat16 g_ph[NPROT * NCLS * CC];  // [i][a][c] hi
__device__ __align__(16) __nv_bfloat16 g_pl[NPROT * NCLS * CC];  // [i][a][c] lo
__device__ __align__(16) float g_sim[(size_t)BB * PP];           // [b][i][a]
__device__ __align__(16) float g_acc[BB * NCLS];                 // S_n(b)

// ---------------------------------------------------------------------------
// Portable tensor-core helpers (compute_103-safe: ldmatrix + mma.sync)
// ---------------------------------------------------------------------------
__device__ __forceinline__ uint32_t smem_to_u32(const void* p) {
    uint32_t a;
    asm("{ .reg .u64 t; cvta.to.shared.u64 t, %1; cvt.u32.u64 %0, t; }"
        : "=r"(a) : "l"(p));
    return a;
}

#define SMEM_SWIZZLE_128B(off) ((off) ^ (((off) >> 3) & 0x70))

#define LDSM_X4(r, addr) \
    asm volatile("ldmatrix.sync.aligned.m8n8.x4.shared.b16 {%0,%1,%2,%3}, [%4];" \
                 : "=r"((r)[0]), "=r"((r)[1]), "=r"((r)[2]), "=r"((r)[3]) \
                 : "r"(addr))
#define LDSM_X2(r, addr) \
    asm volatile("ldmatrix.sync.aligned.m8n8.x2.shared.b16 {%0,%1}, [%2];" \
                 : "=r"((r)[0]), "=r"((r)[1]) : "r"(addr))

__device__ __forceinline__ void mma16816(float* d, const uint32_t* a,
                                         const uint32_t* b) {
    asm volatile(
        "mma.sync.aligned.m16n8k16.row.col.f32.bf16.bf16.f32 "
        "{%0,%1,%2,%3}, {%4,%5,%6,%7}, {%8,%9}, {%0,%1,%2,%3};"
        : "+f"(d[0]), "+f"(d[1]), "+f"(d[2]), "+f"(d[3])
        : "r"(a[0]), "r"(a[1]), "r"(a[2]), "r"(a[3]), "r"(b[0]), "r"(b[1]));
}

// ---------------------------------------------------------------------------
// K1: normalize prototypes over C, split to bf16 hi/lo, reorder [i][a][c]
// ---------------------------------------------------------------------------
__global__ void k1_norm_proto(const float* __restrict__ proto) {
    int p    = blockIdx.x * 8 + (threadIdx.x >> 5);
    int lane = threadIdx.x & 31;
    if (p >= PP) return;
    float v0 = proto[p * CC + lane];
    float v1 = proto[p * CC + lane + 32];
    float ss = v0 * v0 + v1 * v1;
    #pragma unroll
    for (int o = 16; o; o >>= 1) ss += __shfl_xor_sync(0xffffffffu, ss, o);
    float sc = 1.0f / fmaxf(sqrtf(ss), 1e-12f);
    int i = p % NPROT, a = p / NPROT;
    size_t base = (size_t)(i * NCLS + a) * CC;
    float w0 = v0 * sc, w1 = v1 * sc;
    __nv_bfloat16 h0 = __float2bfloat16(w0);
    __nv_bfloat16 h1 = __float2bfloat16(w1);
    g_ph[base + lane]      = h0;
    g_ph[base + lane + 32] = h1;
    g_pl[base + lane]      = __float2bfloat16(w0 - __bfloat162float(h0));
    g_pl[base + lane + 32] = __float2bfloat16(w1 - __bfloat162float(h1));
}

// ---------------------------------------------------------------------------
// K2: normalize conv_features over C, split to bf16 hi/lo, reorder [i][b][c]
// ---------------------------------------------------------------------------
__global__ void k2_norm_x(const float* __restrict__ conv) {
    __shared__ float s[CC * 41];
    __shared__ float rn[WW];
    int b = blockIdx.x;
    int t = threadIdx.x;             // 256
    const float* src = conv + (size_t)b * (CC * WW);
    for (int e = t; e < CC * WW; e += 256) {
        int c = e / WW, w = e % WW;
        s[c * 41 + w] = src[e];
    }
    __syncthreads();
    if (t < WW) {
        float ss = 0.0f;
        #pragma unroll
        for (int c = 0; c < CC; ++c) { float v = s[c * 41 + t]; ss += v * v; }
        rn[t] = 1.0f / fmaxf(sqrtf(ss), 1e-12f);
    }
    __syncthreads();
    for (int e = t; e < WW * CC; e += 256) {
        int i = e / CC, c = e % CC;
        float v = s[c * 41 + i] * rn[i];
        __nv_bfloat16 h = __float2bfloat16(v);
        size_t idx = ((size_t)i * BB + b) * CC + c;
        g_xh[idx] = h;
        g_xl[idx] = __float2bfloat16(v - __bfloat162float(h));
    }
}

// ---------------------------------------------------------------------------
// K3: warp-level bf16 HMMA split GEMM.  Per CTA: 128(b) x 128(a) x 64(c),
//     one i.  sim = Xh*Ph + Xh*Pl + Xl*Ph (fp32 accum).
//     SMEM: 4 SW128-swizzled bf16 tiles (128 rows x 128B = 16KB each).
//     8 warps, each 64(m) x 32(n): 4 m-tiles x 4 n-tiles of m16n8k16.
// ---------------------------------------------------------------------------
#define OFF_AH 0
#define OFF_AL 16384
#define OFF_BH 32768
#define OFF_BL 49152
#define K3_SMEM 65536

extern __shared__ __align__(1024) char sm3[];

__device__ __forceinline__ void gemm_pass(uint32_t baseA, uint32_t baseB,
                                          float (&acc)[4][4][4],
                                          int R, int CA, int NB, int CB,
                                          int sw) {
    #pragma unroll
    for (int ks = 0; ks < 4; ++ks) {
        uint32_t a[4][4];
        #pragma unroll
        for (int mt = 0; mt < 4; ++mt) {
            uint32_t addr = baseA + (uint32_t)((R + mt * 16) * 128
                                   + (((CA + ks * 2) ^ sw) * 16));
            LDSM_X4(a[mt], addr);
        }
        uint32_t b[4][2];
        #pragma unroll
        for (int nt = 0; nt < 4; ++nt) {
            uint32_t addr = baseB + (uint32_t)((NB + nt * 8) * 128
                                   + (((CB + ks * 2) ^ sw) * 16));
            LDSM_X2(b[nt], addr);
        }
        #pragma unroll
        for (int mt = 0; mt < 4; ++mt)
            #pragma unroll
            for (int nt = 0; nt < 4; ++nt)
                mma16816(acc[mt][nt], a[mt], b[nt]);
    }
}

__global__ __launch_bounds__(256, 2) void k3_gemm_tc() {
    uint32_t sb = smem_to_u32(sm3);
    const int t    = threadIdx.x;
    const int w    = t >> 5;
    const int lane = t & 31;
    const int a0 = blockIdx.x * 128;
    const int i  = blockIdx.y;
    const int b0 = blockIdx.z * 128;     // b slowest -> high b written last

    // Fill: 4 tiles x 128 rows x 128B, swizzled STS (16B chunks).
    {
        const float4* Ah = (const float4*)(g_xh + ((size_t)i * BB + b0) * CC);
        const float4* Al = (const float4*)(g_xl + ((size_t)i * BB + b0) * CC);
        const float4* Bh = (const float4*)(g_ph + ((size_t)i * NCLS + a0) * CC);
        const float4* Bl = (const float4*)(g_pl + ((size_t)i * NCLS + a0) * CC);
        #pragma unroll
        for (int j = 0; j < 4; ++j) {
            int chunk = t + j * 256;         // 0..1023
            int row = chunk >> 3;            // 0..127
            int c16 = chunk & 7;             // 16B chunk in 128B row
            uint32_t sw = SMEM_SWIZZLE_128B((uint32_t)(row * 128 + c16 * 16));
            *(float4*)(sm3 + OFF_AH + sw) = Ah[row * 8 + c16];
            *(float4*)(sm3 + OFF_AL + sw) = Al[row * 8 + c16];
            *(float4*)(sm3 + OFF_BH + sw) = Bh[row * 8 + c16];
            *(float4*)(sm3 + OFF_BL + sw) = Bl[row * 8 + c16];
        }
    }
    __syncthreads();

    // Warp tile: wm in {0,1} (64 m-rows), wn in {0..3} (32 n-cols)
    const int m0w = (w & 1) * 64;
    const int n0w = (w >> 1) * 32;
    const int lane16 = lane & 15;
    const int R  = m0w + lane16;         // A ldmatrix row
    const int CA = lane >> 4;            // A chunk base
    const int NB = n0w + (lane16 & 7);   // B ldmatrix row
    const int CB = lane16 >> 3;          // B chunk base
    const int swz = lane16 & 7;          // swizzle key (== row & 7 for both)

    float acc[4][4][4];
    #pragma unroll
    for (int mt = 0; mt < 4; ++mt)
        #pragma unroll
        for (int nt = 0; nt < 4; ++nt)
            #pragma unroll
            for (int q = 0; q < 4; ++q) acc[mt][nt][q] = 0.0f;

    gemm_pass(sb + OFF_AH, sb + OFF_BH, acc, R, CA, NB, CB, swz);
    gemm_pass(sb + OFF_AH, sb + OFF_BL, acc, R, CA, NB, CB, swz);
    gemm_pass(sb + OFF_AL, sb + OFF_BH, acc, R, CA, NB, CB, swz);

    // Epilogue: direct STG.64; each lane-quad covers one full 32B sector.
    const int qr = lane >> 2;            // 0..7
    const int qc = (lane & 3) * 2;       // 0,2,4,6
    #pragma unroll
    for (int mt = 0; mt < 4; ++mt) {
        #pragma unroll
        for (int nt = 0; nt < 4; ++nt) {
            int m = m0w + mt * 16 + qr;
            int n = n0w + nt * 8 + qc;
            float* p = g_sim + (size_t)(b0 + m) * PP + (size_t)i * NCLS + a0 + n;
            *(float2*)p = make_float2(acc[mt][nt][0], acc[mt][nt][1]);
            float* p2 = p + (size_t)8 * PP;
            *(float2*)p2 = make_float2(acc[mt][nt][2], acc[mt][nt][3]);
        }
    }
}

// ---------------------------------------------------------------------------
// K4: per (b, 128-wide a-chunk): vectorized transpose [i][a] -> [a][i],
//     streaming loads/stores; b reversed to ride K3's L2 residency.
// ---------------------------------------------------------------------------
__global__ __launch_bounds__(256) void k4_transpose(float* __restrict__ out_md) {
    __shared__ float s[128 * 41];    // [a][i], pitch 41
    int b  = (int)gridDim.y - 1 - (int)blockIdx.y;   // reverse order
    int a0 = blockIdx.x * 128;
    int t  = threadIdx.x;            // 256
    const float4* src4 = (const float4*)(g_sim + (size_t)b * PP);
    const int a0_4 = a0 >> 2;

    #pragma unroll
    for (int kk = 0; kk < 5; ++kk) {
        int j  = t + kk * 256;       // 0..1279
        int i  = j >> 5;             // 0..39
        int a4 = j & 31;             // 0..31
        float4 v = __ldcs(&src4[i * 128 + a0_4 + a4]);
        float* p = s + (a4 * 4) * 41 + i;
        p[0]   = v.x;
        p[41]  = v.y;
        p[82]  = v.z;
        p[123] = v.w;
    }
    __syncthreads();

    if (t < 128) {
        float sum = 0.0f;
        const float* p = s + t * 41;
        #pragma unroll
        for (int i = 0; i < WW; ++i) sum += p[i];
        g_acc[b * NCLS + a0 + t] = sum;
    }

    float4* dst4 = (float4*)(out_md + (size_t)b * PP + (size_t)a0 * NPROT);
    #pragma unroll
    for (int kk = 0; kk < 5; ++kk) {
        int e4 = t + kk * 256;       // 0..1279
        int a  = e4 / 10;
        int i0 = (e4 - a * 10) * 4;
        const float* p = s + a * 41 + i0;
        float4 o;
        o.x = -p[0]; o.y = -p[1]; o.z = -p[2]; o.w = -p[3];
        __stcs(&dst4[e4], o);
    }
}

// ---------------------------------------------------------------------------
// K5: logits[b][n] = 1.5 * S_n(b) - 0.5 * sum_n S_n(b)
// ---------------------------------------------------------------------------
__global__ void k5_logits(float* __restrict__ out_logits) {
    __shared__ float warpsum[16];
    __shared__ float stot;
    int b = blockIdx.x;
    int t = threadIdx.x;             // 512
    float v = g_acc[b * NCLS + t];
    float sx = v;
    #pragma unroll
    for (int o = 16; o; o >>= 1) sx += __shfl_xor_sync(0xffffffffu, sx, o);
    if ((t & 31) == 0) warpsum[t >> 5] = sx;
    __syncthreads();
    if (t == 0) {
        float x = 0.0f;
        #pragma unroll
        for (int w = 0; w < 16; ++w) x += warpsum[w];
        stot = x;
    }
    __syncthreads();
    out_logits[b * NCLS + t] = 1.5f * v - 0.5f * stot;
}

// ---------------------------------------------------------------------------
// Launch
// ---------------------------------------------------------------------------
extern "C" void kernel_launch(void* const* d_in, const int* in_sizes, int n_in,
                              void* d_out, int out_size) {
    (void)in_sizes; (void)n_in; (void)out_size;
    const float* conv  = (const float*)d_in[0];
    const float* proto = (const float*)d_in[1];
    float* out        = (float*)d_out;
    float* out_logits = out;
    float* out_md     = out + (size_t)BB * NCLS;

    cudaFuncSetAttribute(k3_gemm_tc, cudaFuncAttributeMaxDynamicSharedMemorySize,
                         K3_SMEM);

    k1_norm_proto<<<PP / 8, 256>>>(proto);
    k2_norm_x<<<BB, 256>>>(conv);
    dim3 g3(NCLS / 128, NPROT, BB / 128);    // b slowest
    k3_gemm_tc<<<g3, 256, K3_SMEM>>>();
    dim3 g4(NCLS / 128, BB);
    k4_transpose<<<g4, 256>>>(out_md);
    k5_logits<<<BB, 512>>>(out_logits);
}